// round 1
// baseline (speedup 1.0000x reference)
#include <cuda_runtime.h>

#define B 8
#define T 1024
#define E 128
#define H 8
#define HB (H*B)
#define SCALE 0.08838834764831845f   // 1/sqrt(128)

// ---------------- scratch (static device globals; no allocs allowed) --------
__device__ float g_q[HB * T * E];
__device__ float g_k[HB * T * E];
__device__ float g_v[HB * T * E];
__device__ float g_sel[B * H];

// ---------------- projection GEMM ------------------------------------------
// out[h][b][t][e] = sum_k x[(b,t)][k] * w[k][h*E+e]
// M = B*T = 8192, N = H*E = 1024, K = 128.  blockIdx.z selects q/k/v.
__global__ void __launch_bounds__(256) proj_kernel(const float* __restrict__ x,
                                                   const float* __restrict__ wq,
                                                   const float* __restrict__ wk,
                                                   const float* __restrict__ wv) {
    const float* w;
    float* out;
    if (blockIdx.z == 0)      { w = wq; out = g_q; }
    else if (blockIdx.z == 1) { w = wk; out = g_k; }
    else                      { w = wv; out = g_v; }

    __shared__ float xs[64][68];
    __shared__ float ws[64][68];

    const int tid = threadIdx.x;
    const int m0 = blockIdx.y * 64;
    const int n0 = blockIdx.x * 64;
    const int ty = tid >> 4;   // 0..15
    const int tx = tid & 15;   // 0..15

    float acc[4][4];
    #pragma unroll
    for (int r = 0; r < 4; r++)
        #pragma unroll
        for (int c = 0; c < 4; c++) acc[r][c] = 0.f;

    for (int k0 = 0; k0 < 128; k0 += 64) {
        #pragma unroll
        for (int i = tid; i < 1024; i += 256) {
            int row = i >> 4, c4 = i & 15;
            *(float4*)&xs[row][c4 * 4] =
                *(const float4*)(x + (size_t)(m0 + row) * 128 + k0 + c4 * 4);
        }
        #pragma unroll
        for (int i = tid; i < 1024; i += 256) {
            int row = i >> 4, c4 = i & 15;
            *(float4*)&ws[row][c4 * 4] =
                *(const float4*)(w + (size_t)(k0 + row) * 1024 + n0 + c4 * 4);
        }
        __syncthreads();
        #pragma unroll
        for (int kk = 0; kk < 64; kk++) {
            float a0 = xs[ty * 4 + 0][kk];
            float a1 = xs[ty * 4 + 1][kk];
            float a2 = xs[ty * 4 + 2][kk];
            float a3 = xs[ty * 4 + 3][kk];
            float4 b4 = *(float4*)&ws[kk][tx * 4];
            acc[0][0] = fmaf(a0, b4.x, acc[0][0]);
            acc[0][1] = fmaf(a0, b4.y, acc[0][1]);
            acc[0][2] = fmaf(a0, b4.z, acc[0][2]);
            acc[0][3] = fmaf(a0, b4.w, acc[0][3]);
            acc[1][0] = fmaf(a1, b4.x, acc[1][0]);
            acc[1][1] = fmaf(a1, b4.y, acc[1][1]);
            acc[1][2] = fmaf(a1, b4.z, acc[1][2]);
            acc[1][3] = fmaf(a1, b4.w, acc[1][3]);
            acc[2][0] = fmaf(a2, b4.x, acc[2][0]);
            acc[2][1] = fmaf(a2, b4.y, acc[2][1]);
            acc[2][2] = fmaf(a2, b4.z, acc[2][2]);
            acc[2][3] = fmaf(a2, b4.w, acc[2][3]);
            acc[3][0] = fmaf(a3, b4.x, acc[3][0]);
            acc[3][1] = fmaf(a3, b4.y, acc[3][1]);
            acc[3][2] = fmaf(a3, b4.z, acc[3][2]);
            acc[3][3] = fmaf(a3, b4.w, acc[3][3]);
        }
        __syncthreads();
    }

    const int bb = m0 >> 10;          // batch constant within a 64-row tile
    const int tbase = m0 & 1023;
    #pragma unroll
    for (int r = 0; r < 4; r++) {
        int t = tbase + ty * 4 + r;
        #pragma unroll
        for (int c = 0; c < 4; c++) {
            int n = n0 + tx * 4 + c;
            int hh = n >> 7, e = n & 127;
            out[((size_t)(hh * B + bb) * T + t) * E + e] = acc[r][c];
        }
    }
}

// ---------------- head-gate: sel[b][h] = softmax(mean_t(x) @ w_s^T + b_s) ---
__global__ void __launch_bounds__(128) sel_kernel(const float* __restrict__ x,
                                                  const float* __restrict__ w_s,
                                                  const float* __restrict__ b_s) {
    const int b = blockIdx.x;
    const int tid = threadIdx.x;   // 128 = one per e
    __shared__ float mean_sh[128];
    __shared__ float logit_sh[8];

    const float* xb = x + (size_t)b * T * E;
    float s = 0.f;
    for (int t = 0; t < T; t++) s += xb[(size_t)t * E + tid];
    mean_sh[tid] = s * (1.0f / 1024.0f);
    __syncthreads();
    if (tid < H) {
        float l = b_s[tid];
        const float* wr = w_s + tid * E;
        #pragma unroll 4
        for (int e = 0; e < E; e++) l = fmaf(mean_sh[e], wr[e], l);
        logit_sh[tid] = l;
    }
    __syncthreads();
    if (tid == 0) {
        float mx = logit_sh[0];
        for (int h = 1; h < H; h++) mx = fmaxf(mx, logit_sh[h]);
        float ex[H]; float den = 0.f;
        for (int h = 0; h < H; h++) { ex[h] = expf(logit_sh[h] - mx); den += ex[h]; }
        float inv = 1.0f / den;
        for (int h = 0; h < H; h++) g_sel[b * H + h] = ex[h] * inv;
    }
}

// ---------------- block reduction (sum float + count int), deterministic ----
__device__ __forceinline__ void block_reduce_fi(float& v, int& c, int tid,
                                                float* rf, int* ri) {
    #pragma unroll
    for (int o = 16; o > 0; o >>= 1) {
        v += __shfl_down_sync(0xffffffffu, v, o);
        c += __shfl_down_sync(0xffffffffu, c, o);
    }
    __syncthreads();   // protect rf/ri from previous round's readers
    if ((tid & 31) == 0) { rf[tid >> 5] = v; ri[tid >> 5] = c; }
    __syncthreads();
    v = ((rf[0] + rf[1]) + (rf[2] + rf[3])) + ((rf[4] + rf[5]) + (rf[6] + rf[7]));
    c = ((ri[0] + ri[1]) + (ri[2] + ri[3])) + ((ri[4] + ri[5]) + (ri[6] + ri[7]));
}

// ---------------- fused attention: one block per (b, q) row -----------------
__global__ void __launch_bounds__(256) attn_kernel(const int* __restrict__ mask,
                                                   float* __restrict__ y) {
    const int b = blockIdx.y;
    const int q = blockIdx.x;
    const int tid = threadIdx.x;

    __shared__ int   act[1024];
    __shared__ float s_sh[1024];
    __shared__ float q_sh[128];
    __shared__ float sel_sh[8];
    __shared__ int   scan_sh[256];
    __shared__ int   ntot_sh;
    __shared__ float rf[8];
    __shared__ int   ri[8];

    // ---- build deterministic ordered active list (mask==0 -> unmasked) ----
    const int* mrow = mask + ((size_t)b * T + q) * T;
    int4 mv = *(const int4*)(mrow + tid * 4);
    int f0 = (mv.x == 0), f1 = (mv.y == 0), f2 = (mv.z == 0), f3 = (mv.w == 0);
    scan_sh[tid] = f0 + f1 + f2 + f3;
    if (tid < H) sel_sh[tid] = g_sel[b * H + tid];
    __syncthreads();
    if (tid == 0) {
        int run = 0;
        for (int i = 0; i < 256; i++) { int t = scan_sh[i]; scan_sh[i] = run; run += t; }
        ntot_sh = run;
    }
    __syncthreads();
    const int n_act = ntot_sh;
    {
        int o = scan_sh[tid];
        int kb = tid * 4;
        if (f0) act[o++] = kb;
        if (f1) act[o++] = kb + 1;
        if (f2) act[o++] = kb + 2;
        if (f3) act[o++] = kb + 3;
    }
    __syncthreads();

    float* yrow = y + ((size_t)b * T + q) * E;
    if (n_act == 0) {                // fully-masked row -> exact zeros
        if (tid < E) yrow[tid] = 0.f;
        return;
    }

    const int e_mine = tid & 127;
    const int hf = tid >> 7;
    float acc_reg = 0.f;

    for (int h = 0; h < H; h++) {
        const size_t hb = (size_t)(h * B + b);
        if (tid < E) q_sh[tid] = g_q[(hb * T + q) * E + tid];
        __syncthreads();

        // ---- scores over active set only ----
        const float* Kb = g_k + hb * T * E;
        for (int ii = tid; ii < n_act; ii += 256) {
            const float4* kr = (const float4*)(Kb + (size_t)act[ii] * E);
            float a0 = 0.f, a1 = 0.f, a2 = 0.f, a3 = 0.f;
            #pragma unroll
            for (int j = 0; j < 32; j++) {
                float4 kv = kr[j];
                float4 qv = *(const float4*)&q_sh[j * 4];
                a0 = fmaf(kv.x, qv.x, a0);
                a1 = fmaf(kv.y, qv.y, a1);
                a2 = fmaf(kv.z, qv.z, a2);
                a3 = fmaf(kv.w, qv.w, a3);
            }
            s_sh[ii] = ((a0 + a1) + (a2 + a3)) * SCALE;
        }
        __syncthreads();

        // ---- sparsemax threshold via Michelot iteration (exact) ----
        float tau = -3.0e38f;
        int cnt_prev = -1;
        for (int it = 0; it < 1024; it++) {
            float ls = 0.f; int lc = 0;
            for (int ii = tid; ii < n_act; ii += 256) {
                float v = s_sh[ii];
                if (v > tau) { ls += v; lc++; }
            }
            block_reduce_fi(ls, lc, tid, rf, ri);
            if (lc == cnt_prev || lc == 0) break;   // support stable -> tau final
            tau = (ls - 1.f) / (float)lc;
            cnt_prev = lc;
        }

        // ---- sparse AV gather, gated by sel[b][h] ----
        float local = 0.f;
        const float* Vb = g_v + hb * T * E + e_mine;
        for (int ii = hf; ii < n_act; ii += 2) {
            float p = s_sh[ii] - tau;
            if (p > 0.f) local = fmaf(p, Vb[(size_t)act[ii] * E], local);
        }
        acc_reg = fmaf(sel_sh[h], local, acc_reg);
        __syncthreads();   // s_sh / q_sh reused next head
    }

    // ---- combine the two k-halves and write ----
    s_sh[tid] = acc_reg;
    __syncthreads();
    if (tid < E) yrow[tid] = s_sh[tid] + s_sh[tid + 128];
}

// ---------------- launch -----------------------------------------------------
extern "C" void kernel_launch(void* const* d_in, const int* in_sizes, int n_in,
                              void* d_out, int out_size) {
    (void)in_sizes; (void)n_in; (void)out_size;
    const float* x    = (const float*)d_in[0];
    const int*   mask = (const int*)  d_in[1];
    const float* wq   = (const float*)d_in[2];
    const float* wk   = (const float*)d_in[3];
    const float* wv   = (const float*)d_in[4];
    const float* ws   = (const float*)d_in[5];
    const float* bs   = (const float*)d_in[6];
    float* y = (float*)d_out;

    dim3 gp(16, 128, 3);             // N/64, M/64, {q,k,v}
    proj_kernel<<<gp, 256>>>(x, wq, wk, wv);
    sel_kernel<<<B, 128>>>(x, ws, bs);
    dim3 ga(T, B);
    attn_kernel<<<ga, 256>>>(mask, y);
}

// round 3
// speedup vs baseline: 4.4356x; 4.4356x over previous
#include <cuda_runtime.h>
#include <cstdint>

#define B 8
#define T 1024
#define E 128
#define H 8
#define HB (H*B)
#define SCALE 0.08838834764831845f   // 1/sqrt(128)
#define NEGV (-1e9f)
#define QT 16
#define CH 128
#define KS 132                        // padded K row stride (floats)

// ---------------- scratch (static device globals; no allocs allowed) --------
__device__ float g_q[HB * T * E];
__device__ float g_k[HB * T * E];
__device__ float g_v[HB * T * E];
__device__ float g_sel[B * H];

// ---------------- projection GEMM (unchanged, 172us) ------------------------
__global__ void __launch_bounds__(256) proj_kernel(const float* __restrict__ x,
                                                   const float* __restrict__ wq,
                                                   const float* __restrict__ wk,
                                                   const float* __restrict__ wv) {
    const float* w;
    float* out;
    if (blockIdx.z == 0)      { w = wq; out = g_q; }
    else if (blockIdx.z == 1) { w = wk; out = g_k; }
    else                      { w = wv; out = g_v; }

    __shared__ float xs[64][68];
    __shared__ float ws[64][68];

    const int tid = threadIdx.x;
    const int m0 = blockIdx.y * 64;
    const int n0 = blockIdx.x * 64;
    const int ty = tid >> 4;
    const int tx = tid & 15;

    float acc[4][4];
    #pragma unroll
    for (int r = 0; r < 4; r++)
        #pragma unroll
        for (int c = 0; c < 4; c++) acc[r][c] = 0.f;

    for (int k0 = 0; k0 < 128; k0 += 64) {
        #pragma unroll
        for (int i = tid; i < 1024; i += 256) {
            int row = i >> 4, c4 = i & 15;
            *(float4*)&xs[row][c4 * 4] =
                *(const float4*)(x + (size_t)(m0 + row) * 128 + k0 + c4 * 4);
        }
        #pragma unroll
        for (int i = tid; i < 1024; i += 256) {
            int row = i >> 4, c4 = i & 15;
            *(float4*)&ws[row][c4 * 4] =
                *(const float4*)(w + (size_t)(k0 + row) * 1024 + n0 + c4 * 4);
        }
        __syncthreads();
        #pragma unroll
        for (int kk = 0; kk < 64; kk++) {
            float a0 = xs[ty * 4 + 0][kk];
            float a1 = xs[ty * 4 + 1][kk];
            float a2 = xs[ty * 4 + 2][kk];
            float a3 = xs[ty * 4 + 3][kk];
            float4 b4 = *(float4*)&ws[kk][tx * 4];
            acc[0][0] = fmaf(a0, b4.x, acc[0][0]);
            acc[0][1] = fmaf(a0, b4.y, acc[0][1]);
            acc[0][2] = fmaf(a0, b4.z, acc[0][2]);
            acc[0][3] = fmaf(a0, b4.w, acc[0][3]);
            acc[1][0] = fmaf(a1, b4.x, acc[1][0]);
            acc[1][1] = fmaf(a1, b4.y, acc[1][1]);
            acc[1][2] = fmaf(a1, b4.z, acc[1][2]);
            acc[1][3] = fmaf(a1, b4.w, acc[1][3]);
            acc[2][0] = fmaf(a2, b4.x, acc[2][0]);
            acc[2][1] = fmaf(a2, b4.y, acc[2][1]);
            acc[2][2] = fmaf(a2, b4.z, acc[2][2]);
            acc[2][3] = fmaf(a2, b4.w, acc[2][3]);
            acc[3][0] = fmaf(a3, b4.x, acc[3][0]);
            acc[3][1] = fmaf(a3, b4.y, acc[3][1]);
            acc[3][2] = fmaf(a3, b4.z, acc[3][2]);
            acc[3][3] = fmaf(a3, b4.w, acc[3][3]);
        }
        __syncthreads();
    }

    const int bb = m0 >> 10;
    const int tbase = m0 & 1023;
    #pragma unroll
    for (int r = 0; r < 4; r++) {
        int t = tbase + ty * 4 + r;
        #pragma unroll
        for (int c = 0; c < 4; c++) {
            int n = n0 + tx * 4 + c;
            int hh = n >> 7, e = n & 127;
            out[((size_t)(hh * B + bb) * T + t) * E + e] = acc[r][c];
        }
    }
}

// ---------------- head-gate softmax (unchanged) ------------------------------
__global__ void __launch_bounds__(128) sel_kernel(const float* __restrict__ x,
                                                  const float* __restrict__ w_s,
                                                  const float* __restrict__ b_s) {
    const int b = blockIdx.x;
    const int tid = threadIdx.x;
    __shared__ float mean_sh[128];
    __shared__ float logit_sh[8];

    const float* xb = x + (size_t)b * T * E;
    float s = 0.f;
    for (int t = 0; t < T; t++) s += xb[(size_t)t * E + tid];
    mean_sh[tid] = s * (1.0f / 1024.0f);
    __syncthreads();
    if (tid < H) {
        float l = b_s[tid];
        const float* wr = w_s + tid * E;
        #pragma unroll 4
        for (int e = 0; e < E; e++) l = fmaf(mean_sh[e], wr[e], l);
        logit_sh[tid] = l;
    }
    __syncthreads();
    if (tid == 0) {
        float mx = logit_sh[0];
        for (int h = 1; h < H; h++) mx = fmaxf(mx, logit_sh[h]);
        float ex[H]; float den = 0.f;
        for (int h = 0; h < H; h++) { ex[h] = expf(logit_sh[h] - mx); den += ex[h]; }
        float inv = 1.0f / den;
        for (int h = 0; h < H; h++) g_sel[b * H + h] = ex[h] * inv;
    }
}

// ---------------- cp.async helper -------------------------------------------
__device__ __forceinline__ void cpa16(uint32_t dst, const void* src) {
    asm volatile("cp.async.cg.shared.global [%0], [%1], 16;\n" :: "r"(dst), "l"(src));
}
__device__ __forceinline__ void cpa_commit() {
    asm volatile("cp.async.commit_group;\n");
}

// ---------------- q-tiled fused attention ------------------------------------
// block = (q-tile of 16, b); 256 threads; heads looped inside.
// dyn smem: Kbuf[2][128][132] | s_sh[16][1024] | out_sh[2][16][128] | Qs[16][128]
//           | mb[512] u32 | tau[16] | sel[8] | qscan[17] | full[16]
__global__ void __launch_bounds__(256) attn2_kernel(const int* __restrict__ mask,
                                                    float* __restrict__ y) {
    extern __shared__ float sm[];
    float*    Kb0    = sm;                          // 2*128*132 = 33792 floats
    float*    s_sh   = sm + 2 * CH * KS;            // 16384
    float*    out_sh = s_sh + QT * 1024;            // 4096
    float*    Qs     = out_sh + 2 * QT * E;         // 2048
    uint32_t* mb     = (uint32_t*)(Qs + QT * E);    // 512 words
    float*    tau_sh = (float*)(mb + 512);          // 16
    float*    sel_sh = tau_sh + 16;                 // 8
    int*      qscan  = (int*)(sel_sh + 8);          // 17
    int*      full_sh= qscan + 17;                  // 16
    uint32_t* flat   = (uint32_t*)Kb0;              // aliases K buffers (AV phase)

    const int b   = blockIdx.y;
    const int q0  = blockIdx.x * QT;
    const int tid = threadIdx.x;
    const int e_mine = tid & 127;
    const int hf     = tid >> 7;
    const int krow   = tid & 127;
    const int e0     = hf * 64;
    const int lane   = tid & 15;
    const int qrow   = tid >> 4;
    const unsigned hmask = 0xFFFFu << (tid & 16);   // my 16-lane group in warp

    // zero out accumulators
    #pragma unroll
    for (int i = 0; i < 16; i++) out_sh[tid + i * 256] = 0.f;
    if (tid < H) sel_sh[tid] = g_sel[b * H + tid];

    // build mask bitwords (bit set = masked): 512 words, 2 per thread
    const int* mbase = mask + ((size_t)b * T + q0) * T;
    #pragma unroll
    for (int wi = 0; wi < 2; wi++) {
        int w = tid + wi * 256;
        int q = w >> 5, wk = w & 31;
        const int4* p = (const int4*)(mbase + (size_t)q * T + wk * 32);
        uint32_t word = 0;
        #pragma unroll
        for (int i = 0; i < 8; i++) {
            int4 v = p[i];
            word |= (uint32_t)(v.x != 0) << (i * 4 + 0);
            word |= (uint32_t)(v.y != 0) << (i * 4 + 1);
            word |= (uint32_t)(v.z != 0) << (i * 4 + 2);
            word |= (uint32_t)(v.w != 0) << (i * 4 + 3);
        }
        mb[w] = word;
    }
    __syncthreads();
    if (tid < QT) {
        int c = 0;
        #pragma unroll
        for (int i = 0; i < 32; i++) c += __popc(mb[tid * 32 + i]);
        full_sh[tid] = (c == 1024);
    }
    __syncthreads();

    for (int h = 0; h < H; h++) {
        const size_t hb = (size_t)(h * B + b);
        const float* Kg = g_k + hb * T * E;

        // load Q tile (16x128)
        #pragma unroll
        for (int i = 0; i < 2; i++) {
            int f = tid + i * 256;            // float4 index 0..511
            int j = f >> 5, c4 = f & 31;
            ((float4*)Qs)[j * 32 + c4] =
                ((const float4*)(g_q + (hb * T + q0 + j) * E))[c4];
        }

        // prefetch chunk 0
        {
            const float4* src = (const float4*)Kg;
            uint32_t dbase = (uint32_t)__cvta_generic_to_shared(Kb0);
            #pragma unroll
            for (int i = 0; i < 16; i++) {
                int f = tid + i * 256;
                int r = f >> 5, c4 = f & 31;
                cpa16(dbase + (uint32_t)(r * KS + c4 * 4) * 4, src + f);
            }
            cpa_commit();
        }

        for (int c = 0; c < 8; c++) {
            if (c < 7) {   // prefetch next chunk into other buffer
                const float4* src = (const float4*)(Kg + (size_t)(c + 1) * CH * E);
                float* dstb = Kb0 + ((c + 1) & 1) * (CH * KS);
                uint32_t dbase = (uint32_t)__cvta_generic_to_shared(dstb);
                #pragma unroll
                for (int i = 0; i < 16; i++) {
                    int f = tid + i * 256;
                    int r = f >> 5, c4 = f & 31;
                    cpa16(dbase + (uint32_t)(r * KS + c4 * 4) * 4, src + f);
                }
                cpa_commit();
                asm volatile("cp.async.wait_group 1;\n");
            } else {
                asm volatile("cp.async.wait_group 0;\n");
            }
            __syncthreads();

            // compute scores: this thread = one k-row, one e-half, 16 q accs
            const float* Kc = Kb0 + (c & 1) * (CH * KS) + krow * KS + e0;
            float acc[16];
            #pragma unroll
            for (int j = 0; j < 16; j++) acc[j] = 0.f;
            #pragma unroll
            for (int i = 0; i < 16; i++) {
                float4 kv = *(const float4*)(Kc + i * 4);
                #pragma unroll
                for (int j = 0; j < 16; j++) {
                    float4 qv = *(const float4*)(Qs + j * 128 + e0 + i * 4);
                    acc[j] = fmaf(kv.x, qv.x,
                             fmaf(kv.y, qv.y,
                             fmaf(kv.z, qv.z,
                             fmaf(kv.w, qv.w, acc[j]))));
                }
            }

            // combine e-halves, apply scale + mask
            const int kglob = c * CH + krow;
            if (hf == 0) {
                #pragma unroll
                for (int j = 0; j < 16; j++) s_sh[j * 1024 + kglob] = acc[j];
            }
            __syncthreads();
            if (hf == 1) {
                #pragma unroll
                for (int j = 0; j < 16; j++) {
                    uint32_t word = mb[j * 32 + (kglob >> 5)];
                    float v = ((word >> (kglob & 31)) & 1u)
                              ? NEGV
                              : (acc[j] + s_sh[j * 1024 + kglob]) * SCALE;
                    s_sh[j * 1024 + kglob] = v;
                }
            }
            __syncthreads();
        }

        // ---- sparsemax (Michelot), 16 lanes per q-row ----
        int ex_saved, cnt_saved;
        {
            float tau;
            if (full_sh[qrow]) {
                tau = 3.0e38f;                 // empty support -> zero row
            } else {
                tau = -3.0e38f;
                int prev = -1;
                const float4* s4 = (const float4*)(s_sh + qrow * 1024);
                for (int it = 0; it < 64; it++) {
                    float ls = 0.f; int lc = 0;
                    #pragma unroll
                    for (int i = 0; i < 16; i++) {
                        float4 v = s4[lane + i * 16];
                        if (v.x > tau) { ls += v.x; lc++; }
                        if (v.y > tau) { ls += v.y; lc++; }
                        if (v.z > tau) { ls += v.z; lc++; }
                        if (v.w > tau) { ls += v.w; lc++; }
                    }
                    #pragma unroll
                    for (int o = 8; o; o >>= 1) {
                        ls += __shfl_xor_sync(hmask, ls, o, 16);
                        lc += __shfl_xor_sync(hmask, lc, o, 16);
                    }
                    if (lc == prev || lc == 0) break;
                    tau = (ls - 1.f) / (float)lc;
                    prev = lc;
                }
            }
            if (lane == 0) tau_sh[qrow] = tau;

            // count my support entries + lane prefix
            int cnt = 0;
            const float4* s4 = (const float4*)(s_sh + qrow * 1024);
            #pragma unroll
            for (int i = 0; i < 16; i++) {
                float4 v = s4[lane + i * 16];
                cnt += (v.x > tau) + (v.y > tau) + (v.z > tau) + (v.w > tau);
            }
            int incl = cnt;
            #pragma unroll
            for (int o = 1; o < 16; o <<= 1) {
                int t = __shfl_up_sync(0xffffffffu, incl, o, 16);
                if (lane >= o) incl += t;
            }
            ex_saved = incl - cnt;
            cnt_saved = cnt;
            if (lane == 15) qscan[qrow] = incl;
        }
        __syncthreads();
        if (tid == 0) {
            int run = 0;
            #pragma unroll
            for (int i = 0; i < 16; i++) { int t = qscan[i]; qscan[i] = run; run += t; }
            qscan[16] = run;
        }
        __syncthreads();

        // write flat support list (aliases K buffers — chunks consumed)
        if (cnt_saved > 0) {
            float mytau = tau_sh[qrow];
            int off = qscan[qrow] + ex_saved;
            const float4* s4 = (const float4*)(s_sh + qrow * 1024);
            #pragma unroll
            for (int i = 0; i < 16; i++) {
                int kbase = (lane + i * 16) * 4;
                float4 v = s4[lane + i * 16];
                if (v.x > mytau) flat[off++] = ((uint32_t)qrow << 16) | kbase;
                if (v.y > mytau) flat[off++] = ((uint32_t)qrow << 16) | (kbase + 1);
                if (v.z > mytau) flat[off++] = ((uint32_t)qrow << 16) | (kbase + 2);
                if (v.w > mytau) flat[off++] = ((uint32_t)qrow << 16) | (kbase + 3);
            }
        }
        __syncthreads();

        // ---- sparse AV over flat support list ----
        {
            const int ntot = qscan[16];
            const float selh = sel_sh[h];
            const float* Vg = g_v + hb * T * E + e_mine;
            float* op = out_sh + hf * (QT * E);
            #pragma unroll 2
            for (int idx = hf; idx < ntot; idx += 2) {
                uint32_t ent = flat[idx];
                int q = ent >> 16, k = ent & 0xffff;
                float p = (s_sh[q * 1024 + k] - tau_sh[q]) * selh;
                op[q * E + e_mine] = fmaf(p, Vg[(size_t)k * E], op[q * E + e_mine]);
            }
        }
        __syncthreads();
    }

    // epilogue: combine halves, write y
    float* yb = y + ((size_t)b * T + q0) * E;
    #pragma unroll
    for (int i = 0; i < 8; i++) {
        int f = tid + i * 256;           // 0..2047
        int q = f >> 7, e = f & 127;
        yb[(size_t)q * E + e] = out_sh[q * E + e] + out_sh[QT * E + q * E + e];
    }
}

// ---------------- launch -----------------------------------------------------
extern "C" void kernel_launch(void* const* d_in, const int* in_sizes, int n_in,
                              void* d_out, int out_size) {
    (void)in_sizes; (void)n_in; (void)out_size;
    const float* x    = (const float*)d_in[0];
    const int*   mask = (const int*)  d_in[1];
    const float* wq   = (const float*)d_in[2];
    const float* wk   = (const float*)d_in[3];
    const float* wv   = (const float*)d_in[4];
    const float* ws   = (const float*)d_in[5];
    const float* bs   = (const float*)d_in[6];
    float* y = (float*)d_out;

    // dyn smem: Kbuf 135168 + s 65536 + out 16384 + Q 8192 + mb 2048 + misc 256
    const int smem_bytes = (2*CH*KS + QT*1024 + 2*QT*E + QT*E) * 4 + 2048 + 256;
    cudaFuncSetAttribute(attn2_kernel,
                         cudaFuncAttributeMaxDynamicSharedMemorySize, smem_bytes);

    dim3 gp(16, 128, 3);
    proj_kernel<<<gp, 256>>>(x, wq, wk, wv);
    sel_kernel<<<B, 128>>>(x, ws, bs);
    dim3 ga(T / QT, B);
    attn2_kernel<<<ga, 256, smem_bytes>>>(mask, y);
}